// round 5
// baseline (speedup 1.0000x reference)
#include <cuda_runtime.h>
#include <cstdint>

// Blur: depthwise 4x4 FIR (separable [1,3,3,1] ⊗ [1,3,3,1] / 16), pad (1,1).
// Input (4,128,513,513) f32 -> Output (4,128,512,512) f32.
//
// Round-5: cp.async (LDGSTS) row staging, prefetch distance 2, ring of 4
// warp-private row buffers. No gmem->register->smem coupling: the async copy
// unit keeps up to 15 outstanding 4B copies per lane while the warp computes.
// Boundary cols/rows handled with the src-size=0 zero-fill form (no masks).
// Compute: horizontal FIR from two aligned LDS.128/thread (4 cols/thread),
// vertical FIR in a 4-entry register ring, one STG.128/thread/row.

#define W_IN   513
#define H_IN   513
#define W_OUT  512
#define H_OUT  512
#define STRIP  64
#define BUFSZ  160      // 132 used; padded
#define NPLANE 512      // 4*128

__device__ __forceinline__ void cp_async4(uint32_t dst, const float* src, bool pred)
{
    int sz = pred ? 4 : 0;   // src-size 0 -> zero-fill destination
    asm volatile("cp.async.ca.shared.global [%0], [%1], 4, %2;\n"
                 :: "r"(dst), "l"(src), "r"(sz));
}
__device__ __forceinline__ void cp_commit()
{
    asm volatile("cp.async.commit_group;\n" ::: "memory");
}
template <int N>
__device__ __forceinline__ void cp_wait()
{
    asm volatile("cp.async.wait_group %0;\n" :: "n"(N) : "memory");
}

__global__ __launch_bounds__(128, 10)
void blur_cpasync_kernel(const float* __restrict__ in, float* __restrict__ out)
{
    __shared__ float sbuf[4][4][BUFSZ];   // [warp][ring slot][idx]

    const int tid   = threadIdx.x;
    const int warp  = tid >> 5;
    const int lane  = tid & 31;
    const int plane = blockIdx.y;
    const int y0    = blockIdx.x * STRIP;
    const int wx0   = warp << 7;          // warp's first output col

    const float* ip = in  + (size_t)plane * (W_IN  * H_IN);
    float*       op = out + (size_t)plane * (W_OUT * H_OUT);

    // Window: buf[i] = in[row][wx0 - 1 + i], i in [0,131). Lane handles
    // idx = lane + 32k, k = 0..4 (smem byte lane*4 + 128k).
    const int  goff = wx0 - 1 + lane;
    const bool p0   = (goff >= 0);                       // only warp0 lane0 false
    const bool p4   = (lane < 3) && (goff + 128 < W_IN); // idx<131 && in range
    const int  c0   = max(goff, 0);
    const int  c4   = min(goff + 128, W_IN - 1);

    const uint32_t sbase =
        (uint32_t)__cvta_generic_to_shared(&sbuf[warp][0][0]) + (uint32_t)(lane << 2);

    // Stage row r asynchronously into ring slot (r - y0 + 1) & 3.
    auto stage = [&](int r) {
        const bool rv = ((unsigned)r < (unsigned)H_IN);
        const float* __restrict__ rp = ip + (size_t)(rv ? r : 0) * W_IN;
        const uint32_t sb = sbase + (uint32_t)(((r - y0 + 1) & 3) * (BUFSZ * 4));
        cp_async4(sb          , rp + c0       , rv && p0);
        cp_async4(sb + 128    , rp + goff + 32, rv);
        cp_async4(sb + 128 * 2, rp + goff + 64, rv);
        cp_async4(sb + 128 * 3, rp + goff + 96, rv);
        cp_async4(sb + 128 * 4, rp + c4       , rv && p4);
        cp_commit();
    };

    // Horizontal FIR: window buf[4l .. 4l+6] = in[x0-1 .. x0+5], x0 = wx0+4l.
    auto hcalc = [&](int slot) -> float4 {
        const float* __restrict__ buf = &sbuf[warp][slot][0];
        float4 a = *reinterpret_cast<const float4*>(buf + 4 * lane);       // x0-1..x0+2
        float4 c = *reinterpret_cast<const float4*>(buf + 4 * lane + 4);   // x0+3..x0+6
        float4 h;
        h.x = a.x + 3.0f * (a.y + a.z) + a.w;
        h.y = a.y + 3.0f * (a.z + a.w) + c.x;
        h.z = a.z + 3.0f * (a.w + c.x) + c.y;
        h.w = a.w + 3.0f * (c.x + c.y) + c.z;
        return h;
    };

    float4 h[4];
    // Prologue: keep 2 rows in flight beyond the one being consumed.
    stage(y0 - 1);
    stage(y0);
    stage(y0 + 1);
    cp_wait<2>(); __syncwarp(); h[0] = hcalc(0);         // row y0-1
    stage(y0 + 2);
    cp_wait<2>(); __syncwarp(); h[1] = hcalc(1);         // row y0
    stage(y0 + 3);
    cp_wait<2>(); __syncwarp(); h[2] = hcalc(2);         // row y0+1

    #pragma unroll 4
    for (int i = 0; i < STRIP; ++i) {
        stage(y0 + 4 + i);            // rows past the strip zero-fill harmlessly
        cp_wait<2>(); __syncwarp();   // row y0+2+i (slot (i+3)&3) is ready
        float4 hd = hcalc((i + 3) & 3);
        h[(i + 3) & 3] = hd;
        float4 ha = h[ i      & 3];
        float4 hb = h[(i + 1) & 3];
        float4 hc = h[(i + 2) & 3];

        float4 o;
        o.x = (ha.x + hd.x + 3.0f * (hb.x + hc.x)) * 0.0625f;
        o.y = (ha.y + hd.y + 3.0f * (hb.y + hc.y)) * 0.0625f;
        o.z = (ha.z + hd.z + 3.0f * (hb.z + hc.z)) * 0.0625f;
        o.w = (ha.w + hd.w + 3.0f * (hb.w + hc.w)) * 0.0625f;

        *reinterpret_cast<float4*>(op + (size_t)(y0 + i) * W_OUT + wx0 + 4 * lane) = o;
    }
}

extern "C" void kernel_launch(void* const* d_in, const int* in_sizes, int n_in,
                              void* d_out, int out_size)
{
    const float* in  = (const float*)d_in[0];
    float*       out = (float*)d_out;
    // d_in[1] is the 4x4 FIR buffer: fixed normalized [1,3,3,1] outer product
    // * factor^2 == ([1,3,3,1] ⊗ [1,3,3,1]) / 16, folded into the constants.

    dim3 grid(H_OUT / STRIP, NPLANE);   // (8, 512)
    blur_cpasync_kernel<<<grid, 128>>>(in, out);
}

// round 6
// speedup vs baseline: 1.0410x; 1.0410x over previous
#include <cuda_runtime.h>

// Blur: depthwise 4x4 FIR (separable [1,3,3,1] ⊗ [1,3,3,1] / 16), pad (1,1).
// Input (4,128,513,513) f32 -> Output (4,128,512,512) f32.
//
// Round-6: R2 staging mechanics (LDG.32 x5 -> STS x5, predicated edges),
// but TWO rows per iteration: 10 independent LDGs batched before a single
// __syncwarp (syncwarp is a fence, so per-sync LDG count == per-warp MLP).
// 8-slot warp-private smem ring (reuse distance >= 3 iterations => the
// per-iteration syncwarp alone orders WAR). Horizontal FIR from two aligned
// LDS.128/thread; vertical FIR over a 5-deep rolling h window; two
// STG.128/thread per iteration.

#define W_IN   513
#define H_IN   513
#define W_OUT  512
#define H_OUT  512
#define STRIP  64
#define BUFSZ  160      // idx 0..130 used; padded
#define NSLOT  8
#define NPLANE 512      // 4*128

__global__ __launch_bounds__(128, 8)
void blur_pair_kernel(const float* __restrict__ in, float* __restrict__ out)
{
    __shared__ float sbuf[4][NSLOT][BUFSZ];   // [warp][ring slot][idx]  (20 KB)

    const int tid   = threadIdx.x;
    const int warp  = tid >> 5;
    const int lane  = tid & 31;
    const int plane = blockIdx.y;
    const int y0    = blockIdx.x * STRIP;
    const int wx0   = warp << 7;              // warp's first output col

    const float* ip = in  + (size_t)plane * (W_IN  * H_IN);
    float*       op = out + (size_t)plane * (W_OUT * H_OUT);

    // Window: buf[i] = in[row][wx0 - 1 + i], i in [0,131). Lane handles
    // idx = lane + 32k, k = 0..4. Only k=0 (left edge: warp0 lane0) and k=4
    // (idx >= 131 or right edge) can be out of range -> predicated loads,
    // unconditional zero-stores keep the pad lanes defined.
    const int  goff = wx0 - 1 + lane;
    const bool m0   = (goff >= 0);
    const bool m4   = (lane < 3) && (goff + 128 < W_IN);

    // Stage input row r into ring slot (pad rows -> zeros, warp-uniform branch).
    auto stage = [&](int r, int slot) {
        float* __restrict__ buf = &sbuf[warp][slot][0];
        if ((unsigned)r < (unsigned)H_IN) {
            const float* __restrict__ rp = ip + (size_t)r * W_IN + goff;
            float v0 = m0 ? __ldg(rp)       : 0.0f;
            float v1 = __ldg(rp + 32);
            float v2 = __ldg(rp + 64);
            float v3 = __ldg(rp + 96);
            float v4 = m4 ? __ldg(rp + 128) : 0.0f;
            buf[lane      ] = v0;
            buf[lane +  32] = v1;
            buf[lane +  64] = v2;
            buf[lane +  96] = v3;
            buf[lane + 128] = v4;
        } else {
            buf[lane      ] = 0.0f;
            buf[lane +  32] = 0.0f;
            buf[lane +  64] = 0.0f;
            buf[lane +  96] = 0.0f;
            buf[lane + 128] = 0.0f;
        }
    };

    // Horizontal FIR: window buf[4l .. 4l+6] = in[x0-1 .. x0+5], x0 = wx0+4l.
    auto hcalc = [&](int slot) -> float4 {
        const float* __restrict__ buf = &sbuf[warp][slot][0];
        float4 a = *reinterpret_cast<const float4*>(buf + 4 * lane);       // x0-1..x0+2
        float4 c = *reinterpret_cast<const float4*>(buf + 4 * lane + 4);   // x0+3..x0+6
        float4 h;
        h.x = a.x + 3.0f * (a.y + a.z) + a.w;
        h.y = a.y + 3.0f * (a.z + a.w) + c.x;
        h.z = a.z + 3.0f * (a.w + c.x) + c.y;
        h.w = a.w + 3.0f * (c.x + c.y) + c.z;
        return h;
    };

    // Prologue: rows y0-1, y0, y0+1 -> slots 0,1,2 (slot = (r - y0 + 1) & 7).
    stage(y0 - 1, 0);
    stage(y0,     1);
    stage(y0 + 1, 2);
    __syncwarp();
    float4 ha = hcalc(0);
    float4 hb = hcalc(1);
    float4 hc = hcalc(2);

    #pragma unroll 4
    for (int i = 0; i < STRIP; i += 2) {
        stage(y0 + 2 + i, (i + 3) & 7);   // 10 independent LDGs batched
        stage(y0 + 3 + i, (i + 4) & 7);
        __syncwarp();
        float4 hd = hcalc((i + 3) & 7);
        float4 he = hcalc((i + 4) & 7);

        float4 o0, o1;
        o0.x = (ha.x + hd.x + 3.0f * (hb.x + hc.x)) * 0.0625f;
        o0.y = (ha.y + hd.y + 3.0f * (hb.y + hc.y)) * 0.0625f;
        o0.z = (ha.z + hd.z + 3.0f * (hb.z + hc.z)) * 0.0625f;
        o0.w = (ha.w + hd.w + 3.0f * (hb.w + hc.w)) * 0.0625f;
        o1.x = (hb.x + he.x + 3.0f * (hc.x + hd.x)) * 0.0625f;
        o1.y = (hb.y + he.y + 3.0f * (hc.y + hd.y)) * 0.0625f;
        o1.z = (hb.z + he.z + 3.0f * (hc.z + hd.z)) * 0.0625f;
        o1.w = (hb.w + he.w + 3.0f * (hc.w + hd.w)) * 0.0625f;

        float* orow = op + (size_t)(y0 + i) * W_OUT + wx0 + 4 * lane;
        *reinterpret_cast<float4*>(orow)         = o0;
        *reinterpret_cast<float4*>(orow + W_OUT) = o1;

        ha = hc; hb = hd; hc = he;        // advance vertical window by 2
    }
}

extern "C" void kernel_launch(void* const* d_in, const int* in_sizes, int n_in,
                              void* d_out, int out_size)
{
    const float* in  = (const float*)d_in[0];
    float*       out = (float*)d_out;
    // d_in[1] is the 4x4 FIR buffer: fixed normalized [1,3,3,1] outer product
    // * factor^2 == ([1,3,3,1] ⊗ [1,3,3,1]) / 16, folded into the constants.

    dim3 grid(H_OUT / STRIP, NPLANE);   // (8, 512)
    blur_pair_kernel<<<grid, 128>>>(in, out);
}

// round 7
// speedup vs baseline: 1.1811x; 1.1345x over previous
#include <cuda_runtime.h>

// Blur: depthwise 4x4 FIR (separable [1,3,3,1] ⊗ [1,3,3,1] / 16), pad (1,1).
// Input (4,128,513,513) f32 -> Output (4,128,512,512) f32.
//
// Round-7: fence-free design. No smem, no __syncwarp. Each warp owns a
// 128-col strip; each thread loads its own 4 cols (dense coalesced LDG.32)
// plus one shared edge-load instruction (lanes 0..2 carry the 3 halo cols).
// Horizontal halo via shfl_up/down; edge lanes patch from the shared load.
// With zero barriers, ptxas pipelines loads across unrolled rows (deep MLP).
// Vertical FIR: rolling 4-entry register ring. One STG.128/thread/row.
// Pad rows: clamped row address + 0/1 multiplier on h (branch-free body).

#define W_IN   513
#define H_IN   513
#define W_OUT  512
#define H_OUT  512
#define STRIP  64
#define NPLANE 512      // 4*128
#define FULL   0xffffffffu

__global__ __launch_bounds__(128, 8)
void blur_shfl_kernel(const float* __restrict__ in, float* __restrict__ out)
{
    const int tid   = threadIdx.x;
    const int warp  = tid >> 5;
    const int lane  = tid & 31;
    const int plane = blockIdx.y;
    const int y0    = blockIdx.x * STRIP;
    const int wx0   = warp << 7;              // warp's first output col
    const int x0    = wx0 + (lane << 2);      // this thread's first output col

    const float* ip = in  + (size_t)plane * (W_IN  * H_IN);
    float*       op = out + (size_t)plane * (W_OUT * H_OUT);

    // Edge-load plan: lane0 -> col wx0-1 (left halo), lane1 -> wx0+128,
    // lane2 -> wx0+129 (right halo). Other lanes idle (predicated off).
    int  ecol;
    bool ep;
    if      (lane == 0) { ecol = wx0 - 1;   ep = (wx0 > 0); }
    else if (lane == 1) { ecol = wx0 + 128; ep = true; }            // <= 512 always
    else if (lane == 2) { ecol = wx0 + 129; ep = (wx0 + 129 < W_IN); }
    else                { ecol = wx0;       ep = false; }

    // Horizontal FIR for input row r (clamped; rm zeroes pad rows).
    auto hrow = [&](int r) -> float4 {
        const int   rc = min(max(r, 0), H_IN - 1);
        const float rm = ((unsigned)r < (unsigned)H_IN) ? 1.0f : 0.0f;
        const float* __restrict__ rp = ip + (size_t)rc * W_IN;

        float v0 = __ldg(rp + x0);
        float v1 = __ldg(rp + x0 + 1);
        float v2 = __ldg(rp + x0 + 2);
        float v3 = __ldg(rp + x0 + 3);
        float e  = ep ? __ldg(rp + ecol) : 0.0f;

        float e1  = __shfl_sync(FULL, e, 1);          // in[wx0+128]
        float e2  = __shfl_sync(FULL, e, 2);          // in[wx0+129]
        float t;
        t = __shfl_up_sync  (FULL, v3, 1); float xm1 = (lane ==  0) ? e  : t;  // in[x0-1]
        t = __shfl_down_sync(FULL, v0, 1); float xp4 = (lane == 31) ? e1 : t;  // in[x0+4]
        t = __shfl_down_sync(FULL, v1, 1); float xp5 = (lane == 31) ? e2 : t;  // in[x0+5]

        float4 h;
        h.x = (xm1 + 3.0f * (v0 + v1) + v2) * rm;
        h.y = (v0  + 3.0f * (v1 + v2) + v3) * rm;
        h.z = (v1  + 3.0f * (v2 + v3) + xp4) * rm;
        h.w = (v2  + 3.0f * (v3 + xp4) + xp5) * rm;
        return h;
    };

    float4 h[4];
    h[0] = hrow(y0 - 1);
    h[1] = hrow(y0);
    h[2] = hrow(y0 + 1);

    #pragma unroll 4
    for (int i = 0; i < STRIP; ++i) {
        float4 hd = hrow(y0 + 2 + i);
        h[(i + 3) & 3] = hd;
        float4 ha = h[ i      & 3];
        float4 hb = h[(i + 1) & 3];
        float4 hc = h[(i + 2) & 3];

        float4 o;
        o.x = (ha.x + hd.x + 3.0f * (hb.x + hc.x)) * 0.0625f;
        o.y = (ha.y + hd.y + 3.0f * (hb.y + hc.y)) * 0.0625f;
        o.z = (ha.z + hd.z + 3.0f * (hb.z + hc.z)) * 0.0625f;
        o.w = (ha.w + hd.w + 3.0f * (hb.w + hc.w)) * 0.0625f;

        *reinterpret_cast<float4*>(op + (size_t)(y0 + i) * W_OUT + x0) = o;
    }
}

extern "C" void kernel_launch(void* const* d_in, const int* in_sizes, int n_in,
                              void* d_out, int out_size)
{
    const float* in  = (const float*)d_in[0];
    float*       out = (float*)d_out;
    // d_in[1] is the 4x4 FIR buffer: fixed normalized [1,3,3,1] outer product
    // * factor^2 == ([1,3,3,1] ⊗ [1,3,3,1]) / 16, folded into the constants.

    dim3 grid(H_OUT / STRIP, NPLANE);   // (8, 512)
    blur_shfl_kernel<<<grid, 128>>>(in, out);
}